// round 1
// baseline (speedup 1.0000x reference)
#include <cuda_runtime.h>
#include <cstdint>

#define NN 256
#define NT 2048
#define NF 128

// scratch (allocation-free rule: __device__ globals)
__device__ float g_adj_hat[NN * NN];
__device__ float g_xw[(size_t)NN * NT * NF];   // 256 MB intermediate

__device__ __forceinline__ uint32_t f2tf32(float x) {
    uint32_t r;
    asm("cvt.rna.tf32.f32 %0, %1;" : "=r"(r) : "f"(x));
    return r;
}

// ---------------------------------------------------------------------------
// Kernel 1: adj_hat = rownorm(adj + I)
// ---------------------------------------------------------------------------
__global__ void adjhat_kernel(const float* __restrict__ adj) {
    __shared__ float red[256];
    int m = blockIdx.x, j = threadIdx.x;
    float v = adj[m * NN + j] + (j == m ? 1.0f : 0.0f);
    red[j] = v;
    __syncthreads();
#pragma unroll
    for (int off = 128; off > 0; off >>= 1) {
        if (j < off) red[j] += red[j + off];
        __syncthreads();
    }
    g_adj_hat[m * NN + j] = v / red[0];
}

// ---------------------------------------------------------------------------
// Generic tf32 GEMM: C[M x N] = A[M x K] @ B[K x N] (+ bias[col & 127])
// Row-major, M % 128 == 0, N % 128 == 0, K % 32 == 0 (all hold here).
// CTA tile 128x128, BK=32, 256 threads = 8 warps (2x4), warp tile 64x32.
// mma.sync.m16n8k8.tf32, explicit cvt.rna on the gmem->smem path.
// Smem strides chosen conflict-free: A stride 36 (bank = 4*row+col over the
// 8x4 frag footprint -> 32 distinct), B stride 136 (bank = 8*k+n -> distinct).
// ---------------------------------------------------------------------------
#define BM 128
#define BN 128
#define BK 32
#define ASTR 36
#define BSTR 136

__global__ void __launch_bounds__(256)
gemm_tf32(const float* __restrict__ A, const float* __restrict__ B,
          float* __restrict__ C, const float* __restrict__ bias,
          int K, int lda, int ldb, int ldc)
{
    __shared__ float As[BM * ASTR];   // [m][k]
    __shared__ float Bs[BK * BSTR];   // [k][n]

    const int tid  = threadIdx.x;
    const int m0   = blockIdx.x * BM;
    const int n0   = blockIdx.y * BN;

    const int warp   = tid >> 5;
    const int lane   = tid & 31;
    const int grp    = lane >> 2;   // 0..7
    const int tg     = lane & 3;    // 0..3
    const int warp_m = (warp & 1) * 64;
    const int warp_n = (warp >> 1) * 32;

    // gmem->smem mapping (float4 per thread, 4 passes each)
    const int a_col  = (tid & 7) * 4;    // k in [0,32)
    const int a_row0 = tid >> 3;         // +p*32, rows [0,128)
    const int b_col  = (tid & 31) * 4;   // n in [0,128)
    const int b_row0 = tid >> 5;         // +p*8, k-rows [0,32)

    const float* Aptr = A + m0 * lda;
    const float* Bptr = B + n0;

    float acc[4][4][4];
#pragma unroll
    for (int i = 0; i < 4; i++)
#pragma unroll
        for (int j = 0; j < 4; j++)
#pragma unroll
            for (int r = 0; r < 4; r++) acc[i][j][r] = 0.0f;

    float4 areg[4], breg[4];

    // prologue: stage 0
#pragma unroll
    for (int p = 0; p < 4; p++)
        areg[p] = *(const float4*)(Aptr + (a_row0 + p * 32) * lda + a_col);
#pragma unroll
    for (int p = 0; p < 4; p++)
        breg[p] = *(const float4*)(Bptr + (b_row0 + p * 8) * ldb + b_col);

    const int S = K / BK;
    for (int s = 0; s < S; s++) {
        // commit current stage to smem with tf32 rounding
#pragma unroll
        for (int p = 0; p < 4; p++) {
            float4 v = areg[p];
            uint4 w;
            w.x = f2tf32(v.x); w.y = f2tf32(v.y);
            w.z = f2tf32(v.z); w.w = f2tf32(v.w);
            *(uint4*)&As[(a_row0 + p * 32) * ASTR + a_col] = w;
        }
#pragma unroll
        for (int p = 0; p < 4; p++) {
            float4 v = breg[p];
            uint4 w;
            w.x = f2tf32(v.x); w.y = f2tf32(v.y);
            w.z = f2tf32(v.z); w.w = f2tf32(v.w);
            *(uint4*)&Bs[(b_row0 + p * 8) * BSTR + b_col] = w;
        }
        __syncthreads();

        // prefetch next stage while tensor pipe works
        if (s + 1 < S) {
            int ks = (s + 1) * BK;
#pragma unroll
            for (int p = 0; p < 4; p++)
                areg[p] = *(const float4*)(Aptr + (a_row0 + p * 32) * lda + ks + a_col);
#pragma unroll
            for (int p = 0; p < 4; p++)
                breg[p] = *(const float4*)(Bptr + (ks + b_row0 + p * 8) * ldb + b_col);
        }

#pragma unroll
        for (int kk = 0; kk < BK; kk += 8) {
            uint32_t af[4][4];
#pragma unroll
            for (int fm = 0; fm < 4; fm++) {
                int mb = warp_m + fm * 16;
                af[fm][0] = __float_as_uint(As[(mb + grp    ) * ASTR + kk + tg    ]);
                af[fm][1] = __float_as_uint(As[(mb + grp + 8) * ASTR + kk + tg    ]);
                af[fm][2] = __float_as_uint(As[(mb + grp    ) * ASTR + kk + tg + 4]);
                af[fm][3] = __float_as_uint(As[(mb + grp + 8) * ASTR + kk + tg + 4]);
            }
            uint32_t bf[4][2];
#pragma unroll
            for (int fn = 0; fn < 4; fn++) {
                int nb = warp_n + fn * 8;
                bf[fn][0] = __float_as_uint(Bs[(kk + tg    ) * BSTR + nb + grp]);
                bf[fn][1] = __float_as_uint(Bs[(kk + tg + 4) * BSTR + nb + grp]);
            }
#pragma unroll
            for (int fm = 0; fm < 4; fm++)
#pragma unroll
                for (int fn = 0; fn < 4; fn++) {
                    asm("mma.sync.aligned.m16n8k8.row.col.f32.tf32.tf32.f32 "
                        "{%0,%1,%2,%3}, {%4,%5,%6,%7}, {%8,%9}, {%0,%1,%2,%3};\n"
                        : "+f"(acc[fm][fn][0]), "+f"(acc[fm][fn][1]),
                          "+f"(acc[fm][fn][2]), "+f"(acc[fm][fn][3])
                        : "r"(af[fm][0]), "r"(af[fm][1]),
                          "r"(af[fm][2]), "r"(af[fm][3]),
                          "r"(bf[fn][0]), "r"(bf[fn][1]));
                }
        }
        __syncthreads();
    }

    // epilogue (+bias for the aggregation GEMM; bias index = col % 128)
    float2 bv[4];
#pragma unroll
    for (int fn = 0; fn < 4; fn++) { bv[fn].x = 0.0f; bv[fn].y = 0.0f; }
    if (bias) {
#pragma unroll
        for (int fn = 0; fn < 4; fn++) {
            int col = n0 + warp_n + fn * 8 + tg * 2;
            int o = col & (NF - 1);
            bv[fn].x = bias[o];
            bv[fn].y = bias[o + 1];
        }
    }
#pragma unroll
    for (int fm = 0; fm < 4; fm++) {
        int r0 = m0 + warp_m + fm * 16 + grp;
#pragma unroll
        for (int fn = 0; fn < 4; fn++) {
            int col = n0 + warp_n + fn * 8 + tg * 2;
            float2 v0, v1;
            v0.x = acc[fm][fn][0] + bv[fn].x;
            v0.y = acc[fm][fn][1] + bv[fn].y;
            v1.x = acc[fm][fn][2] + bv[fn].x;
            v1.y = acc[fm][fn][3] + bv[fn].y;
            *(float2*)(C + r0 * ldc + col)       = v0;
            *(float2*)(C + (r0 + 8) * ldc + col) = v1;
        }
    }
}

// ---------------------------------------------------------------------------
// Launch: adjhat -> GEMM1 (X@W -> g_xw) -> GEMM2 (adj_hat@g_xw + bias -> out)
// ---------------------------------------------------------------------------
extern "C" void kernel_launch(void* const* d_in, const int* in_sizes, int n_in,
                              void* d_out, int out_size) {
    const float* node_feats = (const float*)d_in[0];   // [256,2048,128]
    const float* adj        = (const float*)d_in[1];   // [256,256]
    const float* weight     = (const float*)d_in[2];   // [128,128]
    const float* bias       = (const float*)d_in[3];   // [128]
    float* out = (float*)d_out;

    float* adj_hat = nullptr;
    float* xw = nullptr;
    cudaGetSymbolAddress((void**)&adj_hat, g_adj_hat);
    cudaGetSymbolAddress((void**)&xw, g_xw);

    // 1) normalize adjacency
    adjhat_kernel<<<NN, 256>>>(adj);

    // 2) xw = X @ W : M = 256*2048 = 524288, N = 128, K = 128
    {
        dim3 grid((NN * NT) / BM, NF / BN);   // (4096, 1)
        gemm_tf32<<<grid, 256>>>(node_feats, weight, xw, nullptr,
                                 NF, NF, NF, NF);
    }

    // 3) out = adj_hat @ xw + bias : M = 256, N = 2048*128 = 262144, K = 256
    //    blockIdx.x = m-tile (fastest) so both m-tiles of an n-tile run
    //    back-to-back -> xw B-tile dedups in L2.
    {
        dim3 grid(NN / BM, (NT * NF) / BN);   // (2, 2048)
        gemm_tf32<<<grid, 256>>>(adj_hat, xw, out, bias,
                                 NN, NN, NT * NF, NT * NF);
    }
}

// round 4
// speedup vs baseline: 1.8413x; 1.8413x over previous
#include <cuda_runtime.h>
#include <cuda_fp16.h>
#include <cstdint>

#define NN 256
#define NT 2048
#define NF 128

// ---------------------------------------------------------------------------
// device scratch (allocation-free rule)
// ---------------------------------------------------------------------------
__device__ __half g_adj16[NN * NN];                 // rownorm(adj+I), fp16, [m][k]
__device__ __half g_w16[NF * NF];                   // W fp16, [a][o] row-major
__device__ __half g_xw[(size_t)NN * NT * NF];       // xw fp16, [r=(node,t)][o]

__device__ __forceinline__ uint32_t smem_u32(const void* p) {
    uint32_t a;
    asm("{ .reg .u64 t; cvta.to.shared.u64 t, %1; cvt.u32.u64 %0, t; }" : "=r"(a) : "l"(p));
    return a;
}
__device__ __forceinline__ uint32_t packh2(float x, float y) {
    __half2 h = __floats2half2_rn(x, y);
    return *reinterpret_cast<uint32_t*>(&h);
}

// ---------------------------------------------------------------------------
// prep: blocks 0..255 -> adj_hat row (fp16); block 256 -> W fp16
// ---------------------------------------------------------------------------
__global__ void prep_kernel(const float* __restrict__ adj, const float* __restrict__ W) {
    int j = threadIdx.x;
    if (blockIdx.x < NN) {
        __shared__ float red[256];
        int m = blockIdx.x;
        float v = adj[m * NN + j] + (j == m ? 1.0f : 0.0f);
        red[j] = v;
        __syncthreads();
#pragma unroll
        for (int off = 128; off > 0; off >>= 1) {
            if (j < off) red[j] += red[j + off];
            __syncthreads();
        }
        g_adj16[m * NN + j] = __float2half_rn(v / red[0]);
    } else {
#pragma unroll
        for (int i = 0; i < 64; i++) {
            int idx = j + i * 256;
            g_w16[idx] = __float2half_rn(W[idx]);
        }
    }
}

// ---------------------------------------------------------------------------
// fp16 mma.sync GEMM, CTA tile 128x128, BK=32, double-buffered smem,
// 256 threads = 8 warps (2 x 4), warp tile 64x32, m16n8k16 + ldmatrix.
//
// MODE 0: xw = X @ W        A = X (fp32->fp16 cvt on stage), B = g_w16,  K=128
//         epilogue -> g_xw fp16 [r][o]
// MODE 1: out = adj_hat @ xw + bias
//         A = g_adj16, B = xw rows (k=node, fixed t; K-major natural), K=256
// ---------------------------------------------------------------------------
#define ASTRB 80          // A smem row stride in bytes (40 halfs): 5r mod 8 -> conflict-free
#define ABYTES (128 * ASTRB)
#define BBYTES (32 * 256)

template <int MODE>
__global__ void __launch_bounds__(256, 2)
gemm_hmma(const float* __restrict__ X, float* __restrict__ Cout,
          const float* __restrict__ bias)
{
    __shared__ __align__(128) char sA[2][ABYTES];
    __shared__ __align__(128) char sB[2][BBYTES];

    const int tid = threadIdx.x;
    const int bid = blockIdx.x;
    const int NC = (MODE == 0) ? 4 : 8;       // K/32

    int m0, t = 0;
    if (MODE == 0) m0 = bid * 128;            // rows of X / xw
    else { m0 = (bid & 1) * 128; t = bid >> 1; }

    const int warp   = tid >> 5;
    const int lane   = tid & 31;
    const int grp    = lane >> 2;
    const int tg     = lane & 3;
    const int warp_m = (warp & 1) * 64;
    const int warp_n = (warp >> 1) * 32;

    // producer mappings
    const int rowX = tid >> 2, segA = tid & 3;     // A: 8 halfs (16B) per (row,seg)
    const int krow = tid >> 4, ncB  = tid & 15;    // B: 8 halfs per (k,nc)

    const uint32_t sa0 = smem_u32(&sA[0][0]);
    const uint32_t sb0 = smem_u32(&sB[0][0]);

    float acc[4][4][4];
#pragma unroll
    for (int i = 0; i < 4; i++)
#pragma unroll
        for (int j = 0; j < 4; j++)
#pragma unroll
            for (int r = 0; r < 4; r++) acc[i][j][r] = 0.0f;

    uint4 aS[2], bS[2];

    auto loadA = [&](int c) {
#pragma unroll
        for (int i = 0; i < 2; i++) {
            int row = rowX + i * 64;
            if (MODE == 0) {
                const float4* p = (const float4*)(X + (size_t)(m0 + row) * NF + c * 32 + segA * 8);
                float4 v0 = p[0], v1 = p[1];
                aS[i].x = packh2(v0.x, v0.y); aS[i].y = packh2(v0.z, v0.w);
                aS[i].z = packh2(v1.x, v1.y); aS[i].w = packh2(v1.z, v1.w);
            } else {
                aS[i] = *(const uint4*)(g_adj16 + (m0 + row) * NN + c * 32 + segA * 8);
            }
        }
    };
    auto loadB = [&](int c) {
#pragma unroll
        for (int i = 0; i < 2; i++) {
            int k = krow + i * 16;
            if (MODE == 0)
                bS[i] = *(const uint4*)(g_w16 + (c * 32 + k) * NF + ncB * 8);
            else
                bS[i] = *(const uint4*)(g_xw + ((size_t)(c * 32 + k) * NT + t) * NF + ncB * 8);
        }
    };
    auto stsAB = [&](int s) {
#pragma unroll
        for (int i = 0; i < 2; i++) {
            int row = rowX + i * 64;
            uint32_t ad = sa0 + s * ABYTES + row * ASTRB + segA * 16;
            asm volatile("st.shared.v4.b32 [%0], {%1,%2,%3,%4};"
                         :: "r"(ad), "r"(aS[i].x), "r"(aS[i].y), "r"(aS[i].z), "r"(aS[i].w) : "memory");
        }
#pragma unroll
        for (int i = 0; i < 2; i++) {
            int k = krow + i * 16;
            uint32_t bd = sb0 + s * BBYTES + k * 256 + ((ncB * 16) ^ ((k & 7) << 4));
            asm volatile("st.shared.v4.b32 [%0], {%1,%2,%3,%4};"
                         :: "r"(bd), "r"(bS[i].x), "r"(bS[i].y), "r"(bS[i].z), "r"(bS[i].w) : "memory");
        }
    };

    auto mma_stage = [&](int s) {
        const uint32_t ab = sa0 + s * ABYTES;
        const uint32_t bb = sb0 + s * BBYTES;
        const int lr = lane & 15, lh = lane >> 4;
#pragma unroll
        for (int kk = 0; kk < 2; kk++) {            // two k16 steps per 32-chunk
            const int ke = kk * 16;                 // k element offset
            uint32_t a[4][4];
#pragma unroll
            for (int fm = 0; fm < 4; fm++) {
                uint32_t ad = ab + (warp_m + fm * 16 + lr) * ASTRB + lh * 16 + ke * 2;
                asm volatile("ldmatrix.sync.aligned.m8n8.x4.shared.b16 {%0,%1,%2,%3}, [%4];"
                             : "=r"(a[fm][0]), "=r"(a[fm][1]), "=r"(a[fm][2]), "=r"(a[fm][3])
                             : "r"(ad));
            }
            uint32_t b[2][4];
#pragma unroll
            for (int np = 0; np < 2; np++) {
                int krw = ke + lr;
                uint32_t bn = (uint32_t)(warp_n + np * 16 + lh * 8) * 2;
                uint32_t bd = bb + krw * 256 + (bn ^ ((krw & 7) << 4));
                asm volatile("ldmatrix.sync.aligned.m8n8.x4.trans.shared.b16 {%0,%1,%2,%3}, [%4];"
                             : "=r"(b[np][0]), "=r"(b[np][1]), "=r"(b[np][2]), "=r"(b[np][3])
                             : "r"(bd));
            }
#pragma unroll
            for (int fm = 0; fm < 4; fm++)
#pragma unroll
                for (int fn = 0; fn < 4; fn++) {
                    const int np = fn >> 1, pr = fn & 1;
                    asm volatile(
                        "mma.sync.aligned.m16n8k16.row.col.f32.f16.f16.f32 "
                        "{%0,%1,%2,%3}, {%4,%5,%6,%7}, {%8,%9}, {%0,%1,%2,%3};"
                        : "+f"(acc[fm][fn][0]), "+f"(acc[fm][fn][1]),
                          "+f"(acc[fm][fn][2]), "+f"(acc[fm][fn][3])
                        : "r"(a[fm][0]), "r"(a[fm][1]), "r"(a[fm][2]), "r"(a[fm][3]),
                          "r"(b[np][pr * 2]), "r"(b[np][pr * 2 + 1]));
                }
        }
    };

    // pipeline
    loadA(0); loadB(0);
    stsAB(0);
    __syncthreads();
    for (int c = 0; c < NC; c++) {
        const int s = c & 1;
        if (c + 1 < NC) { loadA(c + 1); loadB(c + 1); }
        mma_stage(s);
        if (c + 1 < NC) {
            stsAB(s ^ 1);
            __syncthreads();
        }
    }

    // epilogue
#pragma unroll
    for (int fm = 0; fm < 4; fm++) {
        const int r0 = m0 + warp_m + fm * 16 + grp;
#pragma unroll
        for (int fn = 0; fn < 4; fn++) {
            const int col = warp_n + fn * 8 + tg * 2;
            if (MODE == 0) {
                __half2 h0 = __floats2half2_rn(acc[fm][fn][0], acc[fm][fn][1]);
                __half2 h1 = __floats2half2_rn(acc[fm][fn][2], acc[fm][fn][3]);
                *(__half2*)(g_xw + (size_t)r0 * NF + col)       = h0;
                *(__half2*)(g_xw + (size_t)(r0 + 8) * NF + col) = h1;
            } else {
                float2 b2 = *(const float2*)(bias + col);
                float2 v0 = { acc[fm][fn][0] + b2.x, acc[fm][fn][1] + b2.y };
                float2 v1 = { acc[fm][fn][2] + b2.x, acc[fm][fn][3] + b2.y };
                *(float2*)(Cout + ((size_t)r0 * NT + t) * NF + col)       = v0;
                *(float2*)(Cout + ((size_t)(r0 + 8) * NT + t) * NF + col) = v1;
            }
        }
    }
}

// ---------------------------------------------------------------------------
extern "C" void kernel_launch(void* const* d_in, const int* in_sizes, int n_in,
                              void* d_out, int out_size) {
    (void)in_sizes; (void)n_in; (void)out_size;
    const float* node_feats = (const float*)d_in[0];   // [256,2048,128]
    const float* adj        = (const float*)d_in[1];   // [256,256]
    const float* weight     = (const float*)d_in[2];   // [128,128]
    const float* bias       = (const float*)d_in[3];   // [128]
    float* out = (float*)d_out;

    // 1) adj_hat fp16 + W fp16
    prep_kernel<<<NN + 1, 256>>>(adj, weight);

    // 2) xw = X @ W : 4096 CTAs, K=128
    gemm_hmma<0><<<(NN * NT) / 128, 256>>>(node_feats, nullptr, nullptr);

    // 3) out = adj_hat @ xw + bias : (2 m-tiles fastest) x 2048 t, K=256
    gemm_hmma<1><<<2 * NT, 256>>>(nullptr, out, bias);
}

// round 5
// speedup vs baseline: 2.0798x; 1.1295x over previous
#include <cuda_runtime.h>
#include <cuda_fp16.h>
#include <cstdint>

#define NN 256
#define NT 2048
#define NF 128

__device__ __half g_adj16[NN * NN];   // rownorm(adj+I), fp16, [m][k]

__device__ __forceinline__ uint32_t smem_u32(const void* p) {
    uint32_t a;
    asm("{ .reg .u64 t; cvta.to.shared.u64 t, %1; cvt.u32.u64 %0, t; }" : "=r"(a) : "l"(p));
    return a;
}
__device__ __forceinline__ uint32_t packh2(float x, float y) {
    __half2 h = __floats2half2_rn(x, y);
    return *reinterpret_cast<uint32_t*>(&h);
}

// ---------------------------------------------------------------------------
// prep: adj_hat rows -> fp16
// ---------------------------------------------------------------------------
__global__ void prep_kernel(const float* __restrict__ adj) {
    __shared__ float red[256];
    int m = blockIdx.x, j = threadIdx.x;
    float v = adj[m * NN + j] + (j == m ? 1.0f : 0.0f);
    red[j] = v;
    __syncthreads();
#pragma unroll
    for (int off = 128; off > 0; off >>= 1) {
        if (j < off) red[j] += red[j + off];
        __syncthreads();
    }
    g_adj16[m * NN + j] = __float2half_rn(v / red[0]);
}

// ---------------------------------------------------------------------------
// Fused GCN kernel: one CTA per t. 512 threads = 16 warps (4m x 4n),
// warp tile 64x32 over the 256x128 output tile; m16n8k16 fp16 mma.
//
// smem map (dynamic, 136 KB):
//   SW  [0,      32768): W fp16, rows a (128) x 256B, XOR-swizzled
//   SXW [32768,  98304): xw slab fp16, rows node (256) x 256B, XOR-swizzled
//   SA  [98304, 139264): A staging, 2 stages x (256 rows x 80B)
// ---------------------------------------------------------------------------
#define SW_OFF   0
#define SXW_OFF  32768
#define SA_OFF   98304
#define ASTAGE   20480
#define SMEM_TOT 139264

__global__ void __launch_bounds__(512, 1)
fused_gcn(const float* __restrict__ X, const float* __restrict__ W,
          float* __restrict__ out, const float* __restrict__ bias)
{
    extern __shared__ __align__(128) char smem[];
    const uint32_t base = smem_u32(smem);
    const uint32_t SW  = base + SW_OFF;
    const uint32_t SXW = base + SXW_OFF;
    const uint32_t SA  = base + SA_OFF;

    const int t    = blockIdx.x;
    const int tid  = threadIdx.x;
    const int warp = tid >> 5;
    const int lane = tid & 31;
    const int lr   = lane & 15, lh = lane >> 4;
    const int grp  = lane >> 2, tg = lane & 3;
    const int warp_m = (warp & 3) * 64;
    const int warp_n = (warp >> 2) * 32;

    // staging map: 16B unit per (row, seg), 2 passes of 512
    const int rowS = tid >> 2;       // +p*128
    const int segS = tid & 3;

    float acc[4][4][4];
    uint4 aS[2];

    auto zero_acc = [&] {
#pragma unroll
        for (int i = 0; i < 4; i++)
#pragma unroll
            for (int j = 0; j < 4; j++)
#pragma unroll
                for (int r = 0; r < 4; r++) acc[i][j][r] = 0.0f;
    };

    auto sts16 = [](uint32_t addr, uint4 v) {
        asm volatile("st.shared.v4.b32 [%0], {%1,%2,%3,%4};"
                     :: "r"(addr), "r"(v.x), "r"(v.y), "r"(v.z), "r"(v.w) : "memory");
    };

    auto loadX = [&](int c) {
#pragma unroll
        for (int p = 0; p < 2; p++) {
            int row = rowS + p * 128;     // node
            const float4* src = (const float4*)(X + ((size_t)row * NT + t) * NF + c * 32 + segS * 8);
            float4 v0 = src[0], v1 = src[1];
            aS[p].x = packh2(v0.x, v0.y); aS[p].y = packh2(v0.z, v0.w);
            aS[p].z = packh2(v1.x, v1.y); aS[p].w = packh2(v1.z, v1.w);
        }
    };
    auto loadAdj = [&](int c) {
#pragma unroll
        for (int p = 0; p < 2; p++) {
            int row = rowS + p * 128;     // m
            aS[p] = *(const uint4*)(g_adj16 + row * NN + c * 32 + segS * 8);
        }
    };
    auto stsA = [&](int s) {
#pragma unroll
        for (int p = 0; p < 2; p++) {
            int row = rowS + p * 128;
            sts16(SA + s * ASTAGE + row * 80 + segS * 16, aS[p]);
        }
    };

    auto mma_stage = [&](int c, int s, uint32_t Bbase) {
        const uint32_t ab = SA + s * ASTAGE;
#pragma unroll
        for (int kk = 0; kk < 2; kk++) {
            const int ke = kk * 16;
            uint32_t a[4][4];
#pragma unroll
            for (int fm = 0; fm < 4; fm++) {
                uint32_t ad = ab + (warp_m + fm * 16 + lr) * 80 + lh * 16 + ke * 2;
                asm volatile("ldmatrix.sync.aligned.m8n8.x4.shared.b16 {%0,%1,%2,%3}, [%4];"
                             : "=r"(a[fm][0]), "=r"(a[fm][1]), "=r"(a[fm][2]), "=r"(a[fm][3])
                             : "r"(ad));
            }
            uint32_t b[2][4];
#pragma unroll
            for (int np = 0; np < 2; np++) {
                int krw = c * 32 + ke + lr;
                uint32_t bn = (uint32_t)(warp_n + np * 16 + lh * 8) * 2;
                uint32_t bd = Bbase + krw * 256 + (bn ^ ((krw & 7) << 4));
                asm volatile("ldmatrix.sync.aligned.m8n8.x4.trans.shared.b16 {%0,%1,%2,%3}, [%4];"
                             : "=r"(b[np][0]), "=r"(b[np][1]), "=r"(b[np][2]), "=r"(b[np][3])
                             : "r"(bd));
            }
#pragma unroll
            for (int fm = 0; fm < 4; fm++)
#pragma unroll
                for (int fn = 0; fn < 4; fn++) {
                    const int np = fn >> 1, pr = fn & 1;
                    asm volatile(
                        "mma.sync.aligned.m16n8k16.row.col.f32.f16.f16.f32 "
                        "{%0,%1,%2,%3}, {%4,%5,%6,%7}, {%8,%9}, {%0,%1,%2,%3};"
                        : "+f"(acc[fm][fn][0]), "+f"(acc[fm][fn][1]),
                          "+f"(acc[fm][fn][2]), "+f"(acc[fm][fn][3])
                        : "r"(a[fm][0]), "r"(a[fm][1]), "r"(a[fm][2]), "r"(a[fm][3]),
                          "r"(b[np][pr * 2]), "r"(b[np][pr * 2 + 1]));
                }
        }
    };

    // ---- prologue: W -> smem (fp16, swizzled), X chunk 0 -> stage 0 ----
#pragma unroll
    for (int p = 0; p < 4; p++) {
        int u = tid + p * 512;
        int row = u >> 4, seg = u & 15;      // row = a, seg*8 = o
        const float4* src = (const float4*)(W + row * NF + seg * 8);
        float4 v0 = src[0], v1 = src[1];
        uint4 w;
        w.x = packh2(v0.x, v0.y); w.y = packh2(v0.z, v0.w);
        w.z = packh2(v1.x, v1.y); w.w = packh2(v1.z, v1.w);
        sts16(SW + row * 256 + ((seg * 16) ^ ((row & 7) << 4)), w);
    }
    loadX(0);
    stsA(0);
    zero_acc();
    __syncthreads();

    // ---- phase 1: xw_slab = X_t @ W  (K=128, 4 chunks) ----
#pragma unroll
    for (int c = 0; c < 4; c++) {
        const int s = c & 1;
        if (c < 3) loadX(c + 1);
        mma_stage(c, s, SW);
        if (c < 3) { stsA(s ^ 1); __syncthreads(); }
    }

    // phase-1 epilogue: acc -> sXW (fp16, swizzled rows = node)
#pragma unroll
    for (int fm = 0; fm < 4; fm++) {
        const int r0 = warp_m + fm * 16 + grp;
#pragma unroll
        for (int fn = 0; fn < 4; fn++) {
            const int cb = (warp_n + fn * 8 + tg * 2) * 2;   // byte col
            uint32_t h0 = packh2(acc[fm][fn][0], acc[fm][fn][1]);
            uint32_t h1 = packh2(acc[fm][fn][2], acc[fm][fn][3]);
            asm volatile("st.shared.b32 [%0], %1;"
                         :: "r"(SXW + r0 * 256 + (cb ^ ((r0 & 7) << 4))), "r"(h0) : "memory");
            asm volatile("st.shared.b32 [%0], %1;"
                         :: "r"(SXW + (r0 + 8) * 256 + (cb ^ (((r0 + 8) & 7) << 4))), "r"(h1) : "memory");
        }
    }
    __syncthreads();
    zero_acc();

    // ---- phase 2: out_t = adj_hat @ xw_slab + bias  (K=256, 8 chunks) ----
    loadAdj(0);
    stsA(0);
    __syncthreads();
#pragma unroll
    for (int c = 0; c < 8; c++) {
        const int s = c & 1;
        if (c < 7) loadAdj(c + 1);
        mma_stage(c, s, SXW);
        if (c < 7) { stsA(s ^ 1); __syncthreads(); }
    }

    // phase-2 epilogue: out[m][t][o] = acc + bias
#pragma unroll
    for (int fm = 0; fm < 4; fm++) {
        const int r0 = warp_m + fm * 16 + grp;
#pragma unroll
        for (int fn = 0; fn < 4; fn++) {
            const int col = warp_n + fn * 8 + tg * 2;
            float2 b2 = *(const float2*)(bias + col);
            float2 v0 = { acc[fm][fn][0] + b2.x, acc[fm][fn][1] + b2.y };
            float2 v1 = { acc[fm][fn][2] + b2.x, acc[fm][fn][3] + b2.y };
            *(float2*)(out + ((size_t)r0 * NT + t) * NF + col)       = v0;
            *(float2*)(out + ((size_t)(r0 + 8) * NT + t) * NF + col) = v1;
        }
    }
}

// ---------------------------------------------------------------------------
extern "C" void kernel_launch(void* const* d_in, const int* in_sizes, int n_in,
                              void* d_out, int out_size) {
    (void)in_sizes; (void)n_in; (void)out_size;
    const float* node_feats = (const float*)d_in[0];   // [256,2048,128]
    const float* adj        = (const float*)d_in[1];   // [256,256]
    const float* weight     = (const float*)d_in[2];   // [128,128]
    const float* bias       = (const float*)d_in[3];   // [128]
    float* out = (float*)d_out;

    cudaFuncSetAttribute(fused_gcn, cudaFuncAttributeMaxDynamicSharedMemorySize, SMEM_TOT);

    prep_kernel<<<NN, 256>>>(adj);
    fused_gcn<<<NT, 512, SMEM_TOT>>>(node_feats, weight, out, bias);
}